// round 5
// baseline (speedup 1.0000x reference)
#include <cuda_runtime.h>
#include <math.h>

#define NN 100000
#define EE 1600000
#define ETOT (EE + NN)

// ---------------- scratch (device globals; no allocation allowed) ----------
__device__ float g_h1[(size_t)NN * 128];   // layer-1 features  x@W1
__device__ float g_out1[(size_t)NN * 128]; // layer-1 aggregated output (in-place ELU)
__device__ float g_as1[NN * 8];
__device__ float g_ad1[NN * 8];
__device__ float g_s1[NN * 8];             // per (node,head) weight sum
__device__ float g_h2[(size_t)NN * 40];    // layer-2 features
__device__ float g_a2s[NN];
__device__ float g_a2d[NN];
__device__ float g_s2[NN];

// ---------------- f32x2 packed-FMA helpers ---------------------------------
__device__ __forceinline__ unsigned long long pk2(float a, float b) {
    unsigned long long r;
    asm("mov.b64 %0, {%1,%2};" : "=l"(r) : "f"(a), "f"(b));
    return r;
}
__device__ __forceinline__ void upk2(unsigned long long v, float& a, float& b) {
    asm("mov.b64 {%0,%1}, %2;" : "=f"(a), "=f"(b) : "l"(v));
}
__device__ __forceinline__ void fma2(unsigned long long& d, unsigned long long a,
                                     unsigned long long b) {
    asm("fma.rn.f32x2 %0, %1, %2, %3;" : "=l"(d) : "l"(a), "l"(b), "l"(d));
}

// Vector float4 reduction — MUST be .global state space (no generic form).
__device__ __forceinline__ void redg4(float4* p, float4 v) {
    asm volatile("red.global.add.v4.f32 [%0], {%1,%2,%3,%4};"
                 :: "l"(__cvta_generic_to_global(p)),
                    "f"(v.x), "f"(v.y), "f"(v.z), "f"(v.w)
                 : "memory");
}
__device__ __forceinline__ void redg1(float* p, float v) {
    asm volatile("red.global.add.f32 [%0], %1;"
                 :: "l"(__cvta_generic_to_global(p)), "f"(v) : "memory");
}

__device__ __forceinline__ float eluf(float x) { return x > 0.f ? x : expm1f(x); }

// ---------------- GEMM1: H1[N,128] = X[N,128] @ W1[128,128] ----------------
// 32 rows / block, 128 threads (one output column each), f32x2 accumulators.
__global__ void gemm1_k(const float* __restrict__ X, const float* __restrict__ W) {
    __shared__ __align__(16) float Xs[32 * 128];
    int row0 = blockIdx.x * 32;
    int tid = threadIdx.x;

    const float4* Xg = (const float4*)(X + (size_t)row0 * 128);
    float4* Xs4 = (float4*)Xs;
    #pragma unroll
    for (int i = tid; i < 32 * 32; i += 128) Xs4[i] = Xg[i];
    __syncthreads();

    int j = tid;
    unsigned long long acc[32];
    #pragma unroll
    for (int r = 0; r < 32; r++) acc[r] = 0ULL;

    const ulonglong2* Xp = (const ulonglong2*)Xs;
    for (int k4 = 0; k4 < 32; k4++) {
        int kb = k4 * 4;
        float w0 = W[(kb + 0) * 128 + j];
        float w1 = W[(kb + 1) * 128 + j];
        float w2 = W[(kb + 2) * 128 + j];
        float w3 = W[(kb + 3) * 128 + j];
        unsigned long long w01 = pk2(w0, w1), w23 = pk2(w2, w3);
        #pragma unroll
        for (int r = 0; r < 32; r++) {
            ulonglong2 xv = Xp[r * 32 + k4];
            fma2(acc[r], xv.x, w01);
            fma2(acc[r], xv.y, w23);
        }
    }
    float* Hp = g_h1 + (size_t)row0 * 128 + j;
    #pragma unroll
    for (int r = 0; r < 32; r++) {
        float lo, hi;
        upk2(acc[r], lo, hi);
        Hp[(size_t)r * 128] = lo + hi;
    }
}

// ---------------- attention logits layer 1: a_src/a_dst [N,8] --------------
__global__ void att1_k(const float* __restrict__ As, const float* __restrict__ Ad) {
    int i = blockIdx.x * blockDim.x + threadIdx.x; // n*8+h
    if (i >= NN * 8) return;
    int h = i & 7;
    const float4* hp = ((const float4*)g_h1) + (size_t)(i >> 3) * 32 + h * 4;
    const float4* sp = ((const float4*)As) + h * 4;
    const float4* dp = ((const float4*)Ad) + h * 4;
    float a = 0.f, b = 0.f;
    #pragma unroll
    for (int q = 0; q < 4; q++) {
        float4 v = hp[q], s = sp[q], d = dp[q];
        a += v.x * s.x + v.y * s.y + v.z * s.z + v.w * s.w;
        b += v.x * d.x + v.y * d.y + v.z * d.z + v.w * d.w;
    }
    g_as1[i] = a;
    g_ad1[i] = b;
}

// ---------------- edge pass layer 1: one warp per edge ---------------------
// lane = h*4+q ; each lane handles 4 channels (float4) of head h.
__global__ void edge1_k(const int* __restrict__ ei) {
    int warp = (blockIdx.x * blockDim.x + threadIdx.x) >> 5;
    if (warp >= ETOT) return;
    int lane = threadIdx.x & 31;
    int s, d;
    if (warp < EE) {
        s = ei[warp];
        d = ei[EE + warp];
    } else {
        s = d = warp - EE;
    }
    if ((unsigned)s >= NN || (unsigned)d >= NN) return;  // defensive (dtype guard)
    int h = lane >> 2;
    int q = lane & 3;
    float a = g_as1[s * 8 + h] + g_ad1[d * 8 + h];
    a = a > 0.f ? a : 0.2f * a;           // leaky_relu
    float w = __expf(a);                  // no max-shift needed (values are O(10))
    if (q == 0) redg1(&g_s1[d * 8 + h], w);
    float4 v = ((const float4*)g_h1)[(size_t)s * 32 + lane];
    float4 m = make_float4(w * v.x, w * v.y, w * v.z, w * v.w);
    redg4(((float4*)g_out1) + (size_t)d * 32 + lane, m);
}

// ---------------- normalize + bias + ELU (in place) ------------------------
__global__ void norm1_k(const float* __restrict__ B1) {
    int i = blockIdx.x * blockDim.x + threadIdx.x; // n*8+h
    if (i >= NN * 8) return;
    int h = i & 7;
    float inv = 1.f / g_s1[i];
    float4* op = ((float4*)g_out1) + (size_t)(i >> 3) * 32 + h * 4;
    const float4* bp = ((const float4*)B1) + h * 4;
    #pragma unroll
    for (int q = 0; q < 4; q++) {
        float4 v = op[q];
        float4 b = bp[q];
        v.x = eluf(v.x * inv + b.x);
        v.y = eluf(v.y * inv + b.y);
        v.z = eluf(v.z * inv + b.z);
        v.w = eluf(v.w * inv + b.w);
        op[q] = v;
    }
}

// ---------------- GEMM2: H2[N,40] = out1[N,128] @ W2[128,40] ---------------
// 32 rows / block, 64 threads (cols padded to 64; j<40 valid).
__global__ void gemm2_k(const float* __restrict__ W) {
    __shared__ __align__(16) float Xs[32 * 128];
    int row0 = blockIdx.x * 32;
    int tid = threadIdx.x;

    const float4* Xg = (const float4*)(g_out1 + (size_t)row0 * 128);
    float4* Xs4 = (float4*)Xs;
    #pragma unroll
    for (int i = tid; i < 32 * 32; i += 64) Xs4[i] = Xg[i];
    __syncthreads();

    int j = tid;
    bool valid = j < 40;
    unsigned long long acc[32];
    #pragma unroll
    for (int r = 0; r < 32; r++) acc[r] = 0ULL;

    const ulonglong2* Xp = (const ulonglong2*)Xs;
    for (int k4 = 0; k4 < 32; k4++) {
        int kb = k4 * 4;
        float w0 = valid ? W[(kb + 0) * 40 + j] : 0.f;
        float w1 = valid ? W[(kb + 1) * 40 + j] : 0.f;
        float w2 = valid ? W[(kb + 2) * 40 + j] : 0.f;
        float w3 = valid ? W[(kb + 3) * 40 + j] : 0.f;
        unsigned long long w01 = pk2(w0, w1), w23 = pk2(w2, w3);
        #pragma unroll
        for (int r = 0; r < 32; r++) {
            ulonglong2 xv = Xp[r * 32 + k4];
            fma2(acc[r], xv.x, w01);
            fma2(acc[r], xv.y, w23);
        }
    }
    if (valid) {
        #pragma unroll
        for (int r = 0; r < 32; r++) {
            float lo, hi;
            upk2(acc[r], lo, hi);
            g_h2[(size_t)(row0 + r) * 40 + j] = lo + hi;
        }
    }
}

// ---------------- attention logits layer 2 ---------------------------------
__global__ void att2_k(const float* __restrict__ As, const float* __restrict__ Ad) {
    int n = blockIdx.x * blockDim.x + threadIdx.x;
    if (n >= NN) return;
    const float4* hp = ((const float4*)g_h2) + (size_t)n * 10;
    float a = 0.f, b = 0.f;
    #pragma unroll
    for (int q = 0; q < 10; q++) {
        float4 v = hp[q];
        float4 s = ((const float4*)As)[q];
        float4 d = ((const float4*)Ad)[q];
        a += v.x * s.x + v.y * s.y + v.z * s.z + v.w * s.w;
        b += v.x * d.x + v.y * d.y + v.z * d.z + v.w * d.w;
    }
    g_a2s[n] = a;
    g_a2d[n] = b;
}

// ---------------- edge pass layer 2: thread per (edge, float4-chunk) -------
__global__ void edge2_k(const int* __restrict__ ei, float* __restrict__ out) {
    int idx = blockIdx.x * blockDim.x + threadIdx.x;
    if (idx >= ETOT * 10) return;
    int e = idx / 10;
    int q = idx - e * 10;
    int s, d;
    if (e < EE) {
        s = ei[e];
        d = ei[EE + e];
    } else {
        s = d = e - EE;
    }
    if ((unsigned)s >= NN || (unsigned)d >= NN) return;  // defensive
    float a = g_a2s[s] + g_a2d[d];
    a = a > 0.f ? a : 0.2f * a;
    float w = __expf(a);
    if (q == 0) redg1(&g_s2[d], w);
    float4 v = ((const float4*)g_h2)[(size_t)s * 10 + q];
    float4 m = make_float4(w * v.x, w * v.y, w * v.z, w * v.w);
    redg4(((float4*)out) + (size_t)d * 10 + q, m);
}

// ---------------- normalize + bias + ELU + log_softmax (warp per node) -----
__global__ void final_k(float* __restrict__ out, const float* __restrict__ B2) {
    int node = (blockIdx.x * blockDim.x + threadIdx.x) >> 5;
    if (node >= NN) return;
    int lane = threadIdx.x & 31;
    bool act = lane < 10;
    float inv = 1.f / g_s2[node];
    float4 v = make_float4(0.f, 0.f, 0.f, 0.f);
    float4 b = make_float4(0.f, 0.f, 0.f, 0.f);
    if (act) {
        v = ((const float4*)out)[(size_t)node * 10 + lane];
        b = ((const float4*)B2)[lane];
    }
    float t0 = eluf(v.x * inv + b.x);
    float t1 = eluf(v.y * inv + b.y);
    float t2 = eluf(v.z * inv + b.z);
    float t3 = eluf(v.w * inv + b.w);
    float mx = act ? fmaxf(fmaxf(t0, t1), fmaxf(t2, t3)) : -3.0e38f;
    #pragma unroll
    for (int off = 16; off; off >>= 1) mx = fmaxf(mx, __shfl_xor_sync(0xffffffffu, mx, off));
    float se = act ? (__expf(t0 - mx) + __expf(t1 - mx) + __expf(t2 - mx) + __expf(t3 - mx)) : 0.f;
    #pragma unroll
    for (int off = 16; off; off >>= 1) se += __shfl_xor_sync(0xffffffffu, se, off);
    float lse = mx + logf(se);
    if (act) {
        float4 o = make_float4(t0 - lse, t1 - lse, t2 - lse, t3 - lse);
        ((float4*)out)[(size_t)node * 10 + lane] = o;
    }
}

// ---------------- launch ----------------------------------------------------
extern "C" void kernel_launch(void* const* d_in, const int* in_sizes, int n_in,
                              void* d_out, int out_size) {
    const float* x = (const float*)d_in[0];
    const int* ei = (const int*)d_in[2];
    const float* W1 = (const float*)d_in[3];
    const float* as1 = (const float*)d_in[4];
    const float* ad1 = (const float*)d_in[5];
    const float* b1 = (const float*)d_in[6];
    const float* W2 = (const float*)d_in[7];
    const float* as2 = (const float*)d_in[8];
    const float* ad2 = (const float*)d_in[9];
    const float* b2 = (const float*)d_in[10];
    float* out = (float*)d_out;

    void *p_out1, *p_s1, *p_s2;
    cudaGetSymbolAddress(&p_out1, g_out1);
    cudaGetSymbolAddress(&p_s1, g_s1);
    cudaGetSymbolAddress(&p_s2, g_s2);

    cudaMemsetAsync(p_out1, 0, (size_t)NN * 128 * sizeof(float));
    cudaMemsetAsync(p_s1, 0, (size_t)NN * 8 * sizeof(float));
    cudaMemsetAsync(p_s2, 0, (size_t)NN * sizeof(float));
    cudaMemsetAsync(d_out, 0, (size_t)out_size * sizeof(float));

    gemm1_k<<<NN / 32, 128>>>(x, W1);
    att1_k<<<(NN * 8 + 255) / 256, 256>>>(as1, ad1);
    edge1_k<<<(ETOT * 32 + 255) / 256, 256>>>(ei);
    norm1_k<<<(NN * 8 + 255) / 256, 256>>>(b1);
    gemm2_k<<<NN / 32, 64>>>(W2);
    att2_k<<<(NN + 255) / 256, 256>>>(as2, ad2);
    edge2_k<<<(ETOT * 10 + 255) / 256, 256>>>(ei, out);
    final_k<<<(NN * 32 + 255) / 256, 256>>>(out, b2);
}

// round 6
// speedup vs baseline: 1.1178x; 1.1178x over previous
#include <cuda_runtime.h>
#include <math.h>

#define NN 100000
#define EE 1600000

// ---------------- scratch (device globals; no allocation allowed) ----------
__device__ float g_h1[(size_t)NN * 128];   // layer-1 features  x@W1
__device__ float g_out1[(size_t)NN * 128]; // layer-1 output (normalized+ELU)
__device__ float g_as1[NN * 8];
__device__ float g_ad1[NN * 8];
__device__ float g_h2[(size_t)NN * 40];    // layer-2 features
__device__ float g_a2s[NN];
__device__ float g_a2d[NN];
// CSR scratch
__device__ int g_cnt[NN];
__device__ int g_rowstart[NN + 1];
__device__ int g_cursor[NN];
__device__ int g_csrc[EE];

// ---------------- f32x2 packed-FMA helpers ---------------------------------
__device__ __forceinline__ unsigned long long pk2(float a, float b) {
    unsigned long long r;
    asm("mov.b64 %0, {%1,%2};" : "=l"(r) : "f"(a), "f"(b));
    return r;
}
__device__ __forceinline__ void upk2(unsigned long long v, float& a, float& b) {
    asm("mov.b64 {%0,%1}, %2;" : "=f"(a), "=f"(b) : "l"(v));
}
__device__ __forceinline__ void fma2(unsigned long long& d, unsigned long long a,
                                     unsigned long long b) {
    asm("fma.rn.f32x2 %0, %1, %2, %3;" : "=l"(d) : "l"(a), "l"(b), "l"(d));
}

__device__ __forceinline__ float eluf(float x) { return x > 0.f ? x : expm1f(x); }
__device__ __forceinline__ float lrelu(float x) { return x > 0.f ? x : 0.2f * x; }

// ---------------- GEMM1: H1[N,128] = X[N,128] @ W1[128,128] ----------------
__global__ void gemm1_k(const float* __restrict__ X, const float* __restrict__ W) {
    __shared__ __align__(16) float Xs[32 * 128];
    int row0 = blockIdx.x * 32;
    int tid = threadIdx.x;

    const float4* Xg = (const float4*)(X + (size_t)row0 * 128);
    float4* Xs4 = (float4*)Xs;
    #pragma unroll
    for (int i = tid; i < 32 * 32; i += 128) Xs4[i] = Xg[i];
    __syncthreads();

    int j = tid;
    unsigned long long acc[32];
    #pragma unroll
    for (int r = 0; r < 32; r++) acc[r] = 0ULL;

    const ulonglong2* Xp = (const ulonglong2*)Xs;
    for (int k4 = 0; k4 < 32; k4++) {
        int kb = k4 * 4;
        float w0 = W[(kb + 0) * 128 + j];
        float w1 = W[(kb + 1) * 128 + j];
        float w2 = W[(kb + 2) * 128 + j];
        float w3 = W[(kb + 3) * 128 + j];
        unsigned long long w01 = pk2(w0, w1), w23 = pk2(w2, w3);
        #pragma unroll
        for (int r = 0; r < 32; r++) {
            ulonglong2 xv = Xp[r * 32 + k4];
            fma2(acc[r], xv.x, w01);
            fma2(acc[r], xv.y, w23);
        }
    }
    float* Hp = g_h1 + (size_t)row0 * 128 + j;
    #pragma unroll
    for (int r = 0; r < 32; r++) {
        float lo, hi;
        upk2(acc[r], lo, hi);
        Hp[(size_t)r * 128] = lo + hi;
    }
}

// ---------------- attention logits layer 1: a_src/a_dst [N,8] --------------
__global__ void att1_k(const float* __restrict__ As, const float* __restrict__ Ad) {
    int i = blockIdx.x * blockDim.x + threadIdx.x; // n*8+h
    if (i >= NN * 8) return;
    int h = i & 7;
    const float4* hp = ((const float4*)g_h1) + (size_t)(i >> 3) * 32 + h * 4;
    const float4* sp = ((const float4*)As) + h * 4;
    const float4* dp = ((const float4*)Ad) + h * 4;
    float a = 0.f, b = 0.f;
    #pragma unroll
    for (int q = 0; q < 4; q++) {
        float4 v = hp[q], s = sp[q], d = dp[q];
        a += v.x * s.x + v.y * s.y + v.z * s.z + v.w * s.w;
        b += v.x * d.x + v.y * d.y + v.z * d.z + v.w * d.w;
    }
    g_as1[i] = a;
    g_ad1[i] = b;
}

// ---------------- CSR build --------------------------------------------------
__global__ void count_k(const int* __restrict__ ei) {
    int e = blockIdx.x * blockDim.x + threadIdx.x;
    if (e >= EE) return;
    int d = ei[EE + e];
    if ((unsigned)d < NN) atomicAdd(&g_cnt[d], 1);
}

#define SCAN_T 1024
#define CHUNK 98  // 1024*98 >= 100000
__global__ void scan_k() {
    __shared__ int sm[SCAN_T];
    int t = threadIdx.x;
    int begn = t * CHUNK;
    int sum = 0;
    for (int i = 0; i < CHUNK; i++) {
        int n = begn + i;
        if (n < NN) sum += g_cnt[n];
    }
    sm[t] = sum;
    __syncthreads();
    for (int off = 1; off < SCAN_T; off <<= 1) {
        int v = (t >= off) ? sm[t - off] : 0;
        __syncthreads();
        sm[t] += v;
        __syncthreads();
    }
    int run = (t > 0) ? sm[t - 1] : 0;
    for (int i = 0; i < CHUNK; i++) {
        int n = begn + i;
        if (n < NN) {
            g_rowstart[n] = run;
            g_cursor[n] = run;
            run += g_cnt[n];
        }
    }
    if (t == SCAN_T - 1) g_rowstart[NN] = run;
}

__global__ void fill_k(const int* __restrict__ ei) {
    int e = blockIdx.x * blockDim.x + threadIdx.x;
    if (e >= EE) return;
    int s = ei[e];
    int d = ei[EE + e];
    if ((unsigned)s >= NN || (unsigned)d >= NN) return;
    int pos = atomicAdd(&g_cursor[d], 1);
    g_csrc[pos] = s;
}

// ---------------- layer-1 aggregation: warp per dst node --------------------
// lane = h*4+q ; each lane owns 4 channels (float4) of head h.
// Every lane of a head computes the identical weight sequence -> the softmax
// denominator needs no shuffles. Fuses normalize + bias + ELU.
__global__ void agg1_k(const float* __restrict__ B1) {
    int node = (blockIdx.x * blockDim.x + threadIdx.x) >> 5;
    if (node >= NN) return;
    int lane = threadIdx.x & 31;
    int h = lane >> 2;

    float adh = g_ad1[node * 8 + h];
    // self-loop contribution
    float w = __expf(lrelu(g_as1[node * 8 + h] + adh));
    float4 v = ((const float4*)g_h1)[(size_t)node * 32 + lane];
    float4 acc = make_float4(w * v.x, w * v.y, w * v.z, w * v.w);
    float ssum = w;

    int e = g_rowstart[node];
    int end = g_rowstart[node + 1];
    for (; e < end; e++) {
        int s = g_csrc[e];  // uniform across warp (broadcast)
        float a = g_as1[s * 8 + h] + adh;
        float we = __expf(lrelu(a));
        float4 hv = ((const float4*)g_h1)[(size_t)s * 32 + lane];
        acc.x += we * hv.x;
        acc.y += we * hv.y;
        acc.z += we * hv.z;
        acc.w += we * hv.w;
        ssum += we;
    }
    float inv = 1.f / ssum;
    float4 b = ((const float4*)B1)[lane];
    float4 o;
    o.x = eluf(acc.x * inv + b.x);
    o.y = eluf(acc.y * inv + b.y);
    o.z = eluf(acc.z * inv + b.z);
    o.w = eluf(acc.w * inv + b.w);
    ((float4*)g_out1)[(size_t)node * 32 + lane] = o;
}

// ---------------- GEMM2: H2[N,40] = out1[N,128] @ W2[128,40] ---------------
__global__ void gemm2_k(const float* __restrict__ W) {
    __shared__ __align__(16) float Xs[32 * 128];
    int row0 = blockIdx.x * 32;
    int tid = threadIdx.x;

    const float4* Xg = (const float4*)(g_out1 + (size_t)row0 * 128);
    float4* Xs4 = (float4*)Xs;
    #pragma unroll
    for (int i = tid; i < 32 * 32; i += 64) Xs4[i] = Xg[i];
    __syncthreads();

    int j = tid;
    bool valid = j < 40;
    unsigned long long acc[32];
    #pragma unroll
    for (int r = 0; r < 32; r++) acc[r] = 0ULL;

    const ulonglong2* Xp = (const ulonglong2*)Xs;
    for (int k4 = 0; k4 < 32; k4++) {
        int kb = k4 * 4;
        float w0 = valid ? W[(kb + 0) * 40 + j] : 0.f;
        float w1 = valid ? W[(kb + 1) * 40 + j] : 0.f;
        float w2 = valid ? W[(kb + 2) * 40 + j] : 0.f;
        float w3 = valid ? W[(kb + 3) * 40 + j] : 0.f;
        unsigned long long w01 = pk2(w0, w1), w23 = pk2(w2, w3);
        #pragma unroll
        for (int r = 0; r < 32; r++) {
            ulonglong2 xv = Xp[r * 32 + k4];
            fma2(acc[r], xv.x, w01);
            fma2(acc[r], xv.y, w23);
        }
    }
    if (valid) {
        #pragma unroll
        for (int r = 0; r < 32; r++) {
            float lo, hi;
            upk2(acc[r], lo, hi);
            g_h2[(size_t)(row0 + r) * 40 + j] = lo + hi;
        }
    }
}

// ---------------- attention logits layer 2 ---------------------------------
__global__ void att2_k(const float* __restrict__ As, const float* __restrict__ Ad) {
    int n = blockIdx.x * blockDim.x + threadIdx.x;
    if (n >= NN) return;
    const float4* hp = ((const float4*)g_h2) + (size_t)n * 10;
    float a = 0.f, b = 0.f;
    #pragma unroll
    for (int q = 0; q < 10; q++) {
        float4 v = hp[q];
        float4 s = ((const float4*)As)[q];
        float4 d = ((const float4*)Ad)[q];
        a += v.x * s.x + v.y * s.y + v.z * s.z + v.w * s.w;
        b += v.x * d.x + v.y * d.y + v.z * d.z + v.w * d.w;
    }
    g_a2s[n] = a;
    g_a2d[n] = b;
}

// ---------------- layer-2 aggregation + ELU + log_softmax: warp per node ----
// Two edges processed per warp iteration: lanes 0-9 (half 0) and lanes 16-25
// (half 1). Halves combined by shfl_xor(16) at the end.
__global__ void agg2_k(float* __restrict__ out, const float* __restrict__ B2) {
    int node = (blockIdx.x * blockDim.x + threadIdx.x) >> 5;
    if (node >= NN) return;
    int lane = threadIdx.x & 31;
    int half = lane >> 4;
    int l = lane & 15;
    bool act = l < 10;

    float a2d = g_a2d[node];
    float4 acc = make_float4(0.f, 0.f, 0.f, 0.f);
    float ssum = 0.f;

    if (half == 0) {  // self-loop in half 0 only
        float w = __expf(lrelu(g_a2s[node] + a2d));
        if (act) {
            float4 v = ((const float4*)g_h2)[(size_t)node * 10 + l];
            acc = make_float4(w * v.x, w * v.y, w * v.z, w * v.w);
        }
        ssum = w;
    }

    int beg = g_rowstart[node];
    int end = g_rowstart[node + 1];
    for (int e = beg + half; e < end; e += 2) {
        int s = g_csrc[e];
        float w = __expf(lrelu(g_a2s[s] + a2d));
        if (act) {
            float4 v = ((const float4*)g_h2)[(size_t)s * 10 + l];
            acc.x += w * v.x;
            acc.y += w * v.y;
            acc.z += w * v.z;
            acc.w += w * v.w;
        }
        ssum += w;
    }
    // combine the two halves
    acc.x += __shfl_xor_sync(0xffffffffu, acc.x, 16);
    acc.y += __shfl_xor_sync(0xffffffffu, acc.y, 16);
    acc.z += __shfl_xor_sync(0xffffffffu, acc.z, 16);
    acc.w += __shfl_xor_sync(0xffffffffu, acc.w, 16);
    ssum  += __shfl_xor_sync(0xffffffffu, ssum, 16);

    float inv = 1.f / ssum;
    float4 t = make_float4(0.f, 0.f, 0.f, 0.f);
    if (act) {
        float4 b = ((const float4*)B2)[l];
        t.x = eluf(acc.x * inv + b.x);
        t.y = eluf(acc.y * inv + b.y);
        t.z = eluf(acc.z * inv + b.z);
        t.w = eluf(acc.w * inv + b.w);
    }
    // log-softmax over the 40 values (duplicated in both halves; max is
    // duplication-safe, the exp-sum counts half 0 only)
    float mx = act ? fmaxf(fmaxf(t.x, t.y), fmaxf(t.z, t.w)) : -3.0e38f;
    #pragma unroll
    for (int off = 16; off; off >>= 1) mx = fmaxf(mx, __shfl_xor_sync(0xffffffffu, mx, off));
    float se = (act && half == 0)
                   ? (__expf(t.x - mx) + __expf(t.y - mx) + __expf(t.z - mx) + __expf(t.w - mx))
                   : 0.f;
    #pragma unroll
    for (int off = 16; off; off >>= 1) se += __shfl_xor_sync(0xffffffffu, se, off);
    float lse = mx + logf(se);
    if (act && half == 0) {
        float4 o = make_float4(t.x - lse, t.y - lse, t.z - lse, t.w - lse);
        ((float4*)out)[(size_t)node * 10 + l] = o;
    }
}

// ---------------- launch ----------------------------------------------------
extern "C" void kernel_launch(void* const* d_in, const int* in_sizes, int n_in,
                              void* d_out, int out_size) {
    const float* x = (const float*)d_in[0];
    const int* ei = (const int*)d_in[2];
    const float* W1 = (const float*)d_in[3];
    const float* as1 = (const float*)d_in[4];
    const float* ad1 = (const float*)d_in[5];
    const float* b1 = (const float*)d_in[6];
    const float* W2 = (const float*)d_in[7];
    const float* as2 = (const float*)d_in[8];
    const float* ad2 = (const float*)d_in[9];
    const float* b2 = (const float*)d_in[10];
    float* out = (float*)d_out;

    void* p_cnt;
    cudaGetSymbolAddress(&p_cnt, g_cnt);
    cudaMemsetAsync(p_cnt, 0, NN * sizeof(int));

    gemm1_k<<<NN / 32, 128>>>(x, W1);
    att1_k<<<(NN * 8 + 255) / 256, 256>>>(as1, ad1);
    count_k<<<(EE + 255) / 256, 256>>>(ei);
    scan_k<<<1, SCAN_T>>>();
    fill_k<<<(EE + 255) / 256, 256>>>(ei);
    agg1_k<<<(NN * 32 + 255) / 256, 256>>>(b1);
    gemm2_k<<<NN / 32, 64>>>(W2);
    att2_k<<<(NN + 255) / 256, 256>>>(as2, ad2);
    agg2_k<<<(NN * 32 + 255) / 256, 256>>>(out, b2);
}